// round 1
// baseline (speedup 1.0000x reference)
#include <cuda_runtime.h>
#include <math.h>

#define DMODEL 2048
#define SEQ    2048
#define BATCH  2
#define NH     16
#define DK     128
#define MROWS  (BATCH*SEQ)   // 4096

// ---------------- scratch (static device globals; no allocation) ----------------
__device__ float g_Q  [(size_t)BATCH*NH*SEQ*DK];   // [bh][s][d]
__device__ float g_Kt [(size_t)BATCH*NH*DK*SEQ];   // [bh][d][s]  (pre-transposed K)
__device__ float g_V  [(size_t)BATCH*NH*SEQ*DK];   // [bh][s][d]
__device__ float g_ctx[(size_t)BATCH*SEQ*DMODEL];  // [b*s][D]
__device__ float g_cs [MROWS*64];
__device__ float g_sn [MROWS*64];

// ---------------- RoPE cos/sin table (fp64 for accuracy) ----------------
__global__ void rope_table_kernel(const int* __restrict__ pos) {
    int idx = blockIdx.x * blockDim.x + threadIdx.x;   // 0 .. MROWS*64-1
    int m = idx >> 6, i = idx & 63;
    // inv_freq = theta^(-(2i)/128), theta = 10000
    double inv = exp(-(double)(2 * i) * (9.210340371976184 /*ln 1e4*/ / 128.0));
    double ang = (double)pos[m] * inv;
    g_cs[idx] = (float)cos(ang);
    g_sn[idx] = (float)sin(ang);
}

// ---------------- fp32 SGEMM 128x128x16, 256 threads, 8x8 microtile ----------------
// MODE 0: Q = X*WQ, rope, store [bh][s][d]
// MODE 1: K = X*WK, rope, store transposed [bh][d][s]
// MODE 2: V = X*WV, store [bh][s][d]
// MODE 3: out = ctx*WO, store row-major [m][D]
template <int MODE>
__global__ __launch_bounds__(256) void gemm_kernel(const float* __restrict__ A,
                                                   const float* __restrict__ W,
                                                   float* __restrict__ OutParam) {
    __shared__ float As[16][132];   // transposed A tile, padded
    __shared__ float Bs[16][128];

    const int m0 = blockIdx.y * 128;
    const int n0 = blockIdx.x * 128;
    const int tid = threadIdx.x;
    const int tx = tid & 15, ty = tid >> 4;

    const float* Ap = (MODE == 3) ? g_ctx : A;

    float acc[8][8];
#pragma unroll
    for (int i = 0; i < 8; i++)
#pragma unroll
        for (int j = 0; j < 8; j++) acc[i][j] = 0.f;

    for (int k0 = 0; k0 < DMODEL; k0 += 16) {
#pragma unroll
        for (int i = 0; i < 2; i++) {
            int idx = i * 256 + tid;          // 512 float4 = 128 rows x 16 cols
            int ar = idx >> 2, ac = (idx & 3) * 4;
            float4 v = *reinterpret_cast<const float4*>(
                &Ap[(size_t)(m0 + ar) * DMODEL + k0 + ac]);
            As[ac + 0][ar] = v.x; As[ac + 1][ar] = v.y;
            As[ac + 2][ar] = v.z; As[ac + 3][ar] = v.w;
        }
#pragma unroll
        for (int i = 0; i < 2; i++) {
            int idx = i * 256 + tid;          // 512 float4 = 16 rows x 128 cols
            int br = idx >> 5, bc = (idx & 31) * 4;
            *reinterpret_cast<float4*>(&Bs[br][bc]) =
                *reinterpret_cast<const float4*>(&W[(size_t)(k0 + br) * DMODEL + n0 + bc]);
        }
        __syncthreads();
#pragma unroll
        for (int k = 0; k < 16; k++) {
            float a[8], b[8];
            *reinterpret_cast<float4*>(&a[0]) = *reinterpret_cast<float4*>(&As[k][ty * 4]);
            *reinterpret_cast<float4*>(&a[4]) = *reinterpret_cast<float4*>(&As[k][64 + ty * 4]);
            *reinterpret_cast<float4*>(&b[0]) = *reinterpret_cast<float4*>(&Bs[k][tx * 4]);
            *reinterpret_cast<float4*>(&b[4]) = *reinterpret_cast<float4*>(&Bs[k][64 + tx * 4]);
#pragma unroll
            for (int i = 0; i < 8; i++)
#pragma unroll
                for (int j = 0; j < 8; j++) acc[i][j] = fmaf(a[i], b[j], acc[i][j]);
        }
        __syncthreads();
    }

    // ---------------- epilogue ----------------
    if (MODE == 3) {
#pragma unroll
        for (int i = 0; i < 8; i++) {
            int gm = m0 + ((i < 4) ? ty * 4 + i : 64 + ty * 4 + (i - 4));
#pragma unroll
            for (int jh = 0; jh < 2; jh++) {
                float4 v = make_float4(acc[i][jh * 4 + 0], acc[i][jh * 4 + 1],
                                       acc[i][jh * 4 + 2], acc[i][jh * 4 + 3]);
                *reinterpret_cast<float4*>(&OutParam[(size_t)gm * DMODEL + n0 + jh * 64 + tx * 4]) = v;
            }
        }
        return;
    }

    const int h  = n0 >> 7;            // whole 128-col block lies in one head
    const int b  = m0 >> 11;           // whole 128-row block lies in one batch
    const int bh = b * NH + h;

    float r[8][8];
    if (MODE == 2) {
#pragma unroll
        for (int i = 0; i < 8; i++)
#pragma unroll
            for (int j = 0; j < 8; j++) r[i][j] = acc[i][j];
    } else {
#pragma unroll
        for (int i = 0; i < 8; i++) {
            int gm = m0 + ((i < 4) ? ty * 4 + i : 64 + ty * 4 + (i - 4));
#pragma unroll
            for (int jh = 0; jh < 2; jh++) {
                int cl = jh * 64 + tx * 4;                 // even local col of pair 0
                int t  = gm * 64 + (cl >> 1);
                float c0 = g_cs[t],     s0 = g_sn[t];
                float c1 = g_cs[t + 1], s1 = g_sn[t + 1];
                float e0 = acc[i][jh * 4 + 0], o0 = acc[i][jh * 4 + 1];
                float e1 = acc[i][jh * 4 + 2], o1 = acc[i][jh * 4 + 3];
                r[i][jh * 4 + 0] = e0 * c0 - o0 * s0;
                r[i][jh * 4 + 1] = e0 * s0 + o0 * c0;
                r[i][jh * 4 + 2] = e1 * c1 - o1 * s1;
                r[i][jh * 4 + 3] = e1 * s1 + o1 * c1;
            }
        }
    }

    if (MODE == 0 || MODE == 2) {
        float* Out = (MODE == 0) ? g_Q : g_V;
#pragma unroll
        for (int i = 0; i < 8; i++) {
            int lr = (i < 4) ? ty * 4 + i : 64 + ty * 4 + (i - 4);
            int srow = (m0 & (SEQ - 1)) + lr;
#pragma unroll
            for (int jh = 0; jh < 2; jh++) {
                float4 v = make_float4(r[i][jh * 4 + 0], r[i][jh * 4 + 1],
                                       r[i][jh * 4 + 2], r[i][jh * 4 + 3]);
                *reinterpret_cast<float4*>(
                    &Out[(size_t)bh * SEQ * DK + (size_t)srow * DK + jh * 64 + tx * 4]) = v;
            }
        }
    } else {  // MODE == 1: transposed K store [bh][d][s], float4 along s
#pragma unroll
        for (int jh = 0; jh < 2; jh++)
#pragma unroll
            for (int j = 0; j < 4; j++) {
                int dcol = jh * 64 + tx * 4 + j;
#pragma unroll
                for (int g = 0; g < 2; g++) {
                    int sbase = (m0 & (SEQ - 1)) + g * 64 + ty * 4;
                    float4 v = make_float4(r[g * 4 + 0][jh * 4 + j], r[g * 4 + 1][jh * 4 + j],
                                           r[g * 4 + 2][jh * 4 + j], r[g * 4 + 3][jh * 4 + j]);
                    *reinterpret_cast<float4*>(
                        &g_Kt[(size_t)bh * DK * SEQ + (size_t)dcol * SEQ + sbase]) = v;
                }
            }
    }
}

// ---------------- causal flash attention: 64 q-rows/block, 64-key tiles ----------------
__global__ __launch_bounds__(256) void flash_kernel() {
    const int qt = blockIdx.x;       // 0..31
    const int bh = blockIdx.y;       // 0..31
    extern __shared__ float sm[];
    float* Qs  = sm;                 // [64][128]
    float* Kts = sm + 8192;          // [128][64]
    float* Vs  = sm + 16384;         // [64][128]
    float* Ps  = sm + 24576;         // [64][64]

    const int tid = threadIdx.x;
    const int tx = tid & 15, ty = tid >> 4;

    const float* Qg  = g_Q  + (size_t)bh * SEQ * DK + (size_t)qt * 64 * DK;
    const float* Ktg = g_Kt + (size_t)bh * DK * SEQ;
    const float* Vg  = g_V  + (size_t)bh * SEQ * DK;

#pragma unroll
    for (int i = 0; i < 8; i++) {
        int idx = i * 256 + tid;
        *reinterpret_cast<float4*>(&Qs[idx * 4]) =
            *reinterpret_cast<const float4*>(&Qg[idx * 4]);
    }

    float m_i[4], l_i[4], O[4][8];
#pragma unroll
    for (int i = 0; i < 4; i++) {
        m_i[i] = -1e30f; l_i[i] = 0.f;
#pragma unroll
        for (int j = 0; j < 8; j++) O[i][j] = 0.f;
    }

    const float scale = 0.08838834764831845f;   // 1/sqrt(128)

    for (int kt = 0; kt <= qt; kt++) {
        __syncthreads();   // previous tile fully consumed
#pragma unroll
        for (int i = 0; i < 8; i++) {           // K tile (already d-major)
            int idx = i * 256 + tid;            // 2048 float4
            int d = idx >> 4, c = (idx & 15) * 4;
            *reinterpret_cast<float4*>(&Kts[d * 64 + c]) =
                *reinterpret_cast<const float4*>(&Ktg[(size_t)d * SEQ + kt * 64 + c]);
        }
#pragma unroll
        for (int i = 0; i < 8; i++) {           // V tile
            int idx = i * 256 + tid;
            *reinterpret_cast<float4*>(&Vs[idx * 4]) =
                *reinterpret_cast<const float4*>(&Vg[(size_t)kt * 64 * DK + idx * 4]);
        }
        __syncthreads();

        float sc[4][4];
#pragma unroll
        for (int i = 0; i < 4; i++)
#pragma unroll
            for (int j = 0; j < 4; j++) sc[i][j] = 0.f;

#pragma unroll 4
        for (int kd = 0; kd < 128; kd += 4) {
            float4 a[4], bq[4];
#pragma unroll
            for (int i = 0; i < 4; i++)
                a[i] = *reinterpret_cast<float4*>(&Qs[(ty * 4 + i) * 128 + kd]);
#pragma unroll
            for (int q = 0; q < 4; q++)
                bq[q] = *reinterpret_cast<float4*>(&Kts[(kd + q) * 64 + tx * 4]);
#pragma unroll
            for (int i = 0; i < 4; i++) {
                const float* av = reinterpret_cast<const float*>(&a[i]);
#pragma unroll
                for (int q = 0; q < 4; q++) {
                    const float* bv = reinterpret_cast<const float*>(&bq[q]);
#pragma unroll
                    for (int j = 0; j < 4; j++) sc[i][j] = fmaf(av[q], bv[j], sc[i][j]);
                }
            }
        }

        // scale + causal mask (only diagonal tile needs it)
#pragma unroll
        for (int i = 0; i < 4; i++)
#pragma unroll
            for (int j = 0; j < 4; j++) {
                sc[i][j] *= scale;
                if (kt == qt && (tx * 4 + j) > (ty * 4 + i)) sc[i][j] = -1e30f;
            }

        // online softmax
        float mnew[4], fct[4], rs[4];
#pragma unroll
        for (int i = 0; i < 4; i++) {
            float mx = fmaxf(fmaxf(sc[i][0], sc[i][1]), fmaxf(sc[i][2], sc[i][3]));
#pragma unroll
            for (int off = 1; off < 16; off <<= 1)
                mx = fmaxf(mx, __shfl_xor_sync(0xffffffffu, mx, off));
            mnew[i] = fmaxf(m_i[i], mx);
            fct[i] = __expf(m_i[i] - mnew[i]);
            float s = 0.f;
#pragma unroll
            for (int j = 0; j < 4; j++) {
                sc[i][j] = __expf(sc[i][j] - mnew[i]);
                s += sc[i][j];
            }
#pragma unroll
            for (int off = 1; off < 16; off <<= 1)
                s += __shfl_xor_sync(0xffffffffu, s, off);
            rs[i] = s;
        }
#pragma unroll
        for (int i = 0; i < 4; i++) {
            l_i[i] = l_i[i] * fct[i] + rs[i];
            m_i[i] = mnew[i];
            *reinterpret_cast<float4*>(&Ps[(ty * 4 + i) * 64 + tx * 4]) =
                make_float4(sc[i][0], sc[i][1], sc[i][2], sc[i][3]);
#pragma unroll
            for (int j = 0; j < 8; j++) O[i][j] *= fct[i];
        }
        __syncthreads();

        // O += P @ V
#pragma unroll 4
        for (int k = 0; k < 64; k += 4) {
            float4 p4[4];
#pragma unroll
            for (int i = 0; i < 4; i++)
                p4[i] = *reinterpret_cast<float4*>(&Ps[(ty * 4 + i) * 64 + k]);
#pragma unroll
            for (int q = 0; q < 4; q++) {
                float4 v0 = *reinterpret_cast<float4*>(&Vs[(k + q) * 128 + tx * 4]);
                float4 v1 = *reinterpret_cast<float4*>(&Vs[(k + q) * 128 + 64 + tx * 4]);
                const float* vv0 = reinterpret_cast<const float*>(&v0);
                const float* vv1 = reinterpret_cast<const float*>(&v1);
#pragma unroll
                for (int i = 0; i < 4; i++) {
                    float pv = reinterpret_cast<const float*>(&p4[i])[q];
#pragma unroll
                    for (int j = 0; j < 4; j++) {
                        O[i][j]     = fmaf(pv, vv0[j], O[i][j]);
                        O[i][j + 4] = fmaf(pv, vv1[j], O[i][j + 4]);
                    }
                }
            }
        }
    }

    // epilogue -> g_ctx[b*s][h*128 + d]
    const int b = bh >> 4, h = bh & 15;
#pragma unroll
    for (int i = 0; i < 4; i++) {
        float inv = 1.f / l_i[i];
        int qg = qt * 64 + ty * 4 + i;
        size_t base = ((size_t)(b * SEQ + qg)) * DMODEL + h * 128;
        float4 o0 = make_float4(O[i][0] * inv, O[i][1] * inv, O[i][2] * inv, O[i][3] * inv);
        float4 o1 = make_float4(O[i][4] * inv, O[i][5] * inv, O[i][6] * inv, O[i][7] * inv);
        *reinterpret_cast<float4*>(&g_ctx[base + tx * 4])      = o0;
        *reinterpret_cast<float4*>(&g_ctx[base + 64 + tx * 4]) = o1;
    }
}

// ---------------- launch ----------------
extern "C" void kernel_launch(void* const* d_in, const int* in_sizes, int n_in,
                              void* d_out, int out_size) {
    const float* x   = (const float*)d_in[0];
    const int*   pos = (const int*)  d_in[1];
    const float* WQ  = (const float*)d_in[2];
    const float* WK  = (const float*)d_in[3];
    const float* WV  = (const float*)d_in[4];
    const float* WO  = (const float*)d_in[5];
    float* out = (float*)d_out;

    cudaFuncSetAttribute(flash_kernel, cudaFuncAttributeMaxDynamicSharedMemorySize, 114688);

    rope_table_kernel<<<(MROWS * 64) / 256, 256>>>(pos);

    dim3 gg(16, 32);
    gemm_kernel<0><<<gg, 256>>>(x, WQ, nullptr);
    gemm_kernel<1><<<gg, 256>>>(x, WK, nullptr);
    gemm_kernel<2><<<gg, 256>>>(x, WV, nullptr);

    flash_kernel<<<dim3(32, 32), 256, 114688>>>();

    gemm_kernel<3><<<gg, 256>>>(nullptr, WO, out);
}